// round 1
// baseline (speedup 1.0000x reference)
#include <cuda_runtime.h>

// CGMMTransition: N=10000, L=5, A=6, C=20, C2=20
// Outputs (concatenated in d_out, fp32):
//   p_Q_given_obs        [N, C]           at offset 0
//   transition_posterior [N, L, A, C, C2] at offset N*C
//   rightmost_term       [N, L, A, C, C2] at offset N*C + N*L*A*C*C2

#define LVAL   5
#define AVAL   6
#define CVAL   20
#define C2VAL  20
#define LA     30      // L*A
#define PER_N  12000   // LA*C*C2
#define STATS_N 600    // LA*C2
#define NTHREADS 256

__global__ void __launch_bounds__(NTHREADS)
cgmm_kernel(const float* __restrict__ stats,
            const float* __restrict__ layerS,
            const float* __restrict__ arcS,
            const float* __restrict__ T,
            float* __restrict__ out_pq,
            float* __restrict__ out_tp,
            float* __restrict__ out_rt)
{
    __shared__ float s_stats[STATS_N];
    __shared__ float s_inv[LA];
    __shared__ float s_w[LA];
    __shared__ float s_pq[CVAL];

    const int n   = blockIdx.x;
    const int tid = threadIdx.x;

    // ---- Phase 0: stage stats[n] (600 floats = 150 float4) to shared ----
    // n*600 floats = n*2400 bytes -> always 16B aligned.
    const float4* g_stats4 =
        reinterpret_cast<const float4*>(stats + (size_t)n * STATS_N);
    if (tid < STATS_N / 4) {
        // streamed read: each stats element read exactly once from DRAM
        float4 v = __ldcs(&g_stats4[tid]);
        reinterpret_cast<float4*>(s_stats)[tid] = v;
    }
    if (tid < CVAL) s_pq[tid] = 0.0f;
    __syncthreads();

    // ---- Phase 1: per-(l,a) inverse row-sum and weight ----
    if (tid < LA) {
        float s = 0.0f;
        #pragma unroll
        for (int j = 0; j < C2VAL; ++j) s += s_stats[tid * C2VAL + j];
        s_inv[tid] = (s == 0.0f) ? 1.0f : 1.0f / s;
        s_w[tid]   = layerS[tid / AVAL] * arcS[tid];
    }
    __syncthreads();

    // ---- Phase 2a: p_Q[n,c] = sum_la w*inv * dot(T[la,c,:], stats[n,la,:])
    // 600 rows; T rows hit L1 (48 KB total, resident per SM).
    for (int r = tid; r < LA * CVAL; r += NTHREADS) {
        const int la = r / CVAL;
        const int c  = r % CVAL;   // consecutive lanes -> distinct c (<=2-way conflict)
        const float* trow = T + la * (CVAL * C2VAL) + c * C2VAL;
        const float* srow = s_stats + la * C2VAL;
        float dot = 0.0f;
        #pragma unroll
        for (int j = 0; j < C2VAL; ++j) dot = fmaf(trow[j], srow[j], dot);
        atomicAdd(&s_pq[c], dot * s_w[la] * s_inv[la]);
    }

    // ---- Phase 2b: main elementwise stream (coalesced float4) ----
    // rt = T * stats * inv ; tp = rt * w. 6000 STG.128 / block, streaming.
    const size_t base = (size_t)n * PER_N;   // *4 bytes = 48000 -> 16B aligned
    const float4* T4  = reinterpret_cast<const float4*>(T);
    float4* rt4 = reinterpret_cast<float4*>(out_rt + base);
    float4* tp4 = reinterpret_cast<float4*>(out_tp + base);

    for (int i = tid; i < PER_N / 4; i += NTHREADS) {
        const int e   = i * 4;
        const int la  = e / (CVAL * C2VAL);
        const int c2b = e % C2VAL;           // in {0,4,8,12,16}: no straddle
        const float4 t  = __ldg(&T4[i]);     // L1-cached, coalesced
        const float4 sv = *reinterpret_cast<const float4*>(
                              s_stats + la * C2VAL + c2b);
        const float inv = s_inv[la];
        const float w   = s_w[la];
        float4 r, p;
        r.x = t.x * sv.x * inv;  r.y = t.y * sv.y * inv;
        r.z = t.z * sv.z * inv;  r.w = t.w * sv.w * inv;
        p.x = r.x * w;  p.y = r.y * w;  p.z = r.z * w;  p.w = r.w * w;
        __stcs(&rt4[i], r);   // streaming stores: don't pollute L2
        __stcs(&tp4[i], p);
    }

    __syncthreads();
    if (tid < CVAL) out_pq[(size_t)n * CVAL + tid] = s_pq[tid];
}

extern "C" void kernel_launch(void* const* d_in, const int* in_sizes, int n_in,
                              void* d_out, int out_size)
{
    const float* stats  = (const float*)d_in[0];  // [N, L, A, C2]
    const float* layerS = (const float*)d_in[1];  // [L]
    const float* arcS   = (const float*)d_in[2];  // [L, A]
    const float* T      = (const float*)d_in[3];  // [L, A, C, C2]

    const int N = in_sizes[0] / STATS_N;

    float* out    = (float*)d_out;
    float* out_pq = out;
    float* out_tp = out_pq + (size_t)N * CVAL;
    float* out_rt = out_tp + (size_t)N * PER_N;

    cgmm_kernel<<<N, NTHREADS>>>(stats, layerS, arcS, T,
                                 out_pq, out_tp, out_rt);
}